// round 14
// baseline (speedup 1.0000x reference)
#include <cuda_runtime.h>

#define L 2048
#define CIN 16
#define GROUPS 4

// Tiny tau table: one threshold per (channel, row). 128 KB, L2-resident.
__device__ float g_tau[(size_t)CIN * L];

// ---------------------------------------------------------------------------
// Kernel 1': causal sparsemax THRESHOLD ONLY, one warp per row.
// 16 back-to-back predicated LDG.128 (MLP ~16); Michelot fixed point from
// tight tau0 = max((S-1)/n, max-1); shfl reductions. Writes 1 float per row.
// block = 256 (8 warps = 8 rows), grid = (L/8, CIN).
// ---------------------------------------------------------------------------
__global__ void __launch_bounds__(256) sparsemax_tau(const float* __restrict__ scores) {
    const int tid  = threadIdx.x;
    const int w    = tid >> 5;
    const int lane = tid & 31;
    const int i    = (blockIdx.x << 3) + w;   // data row
    const int c    = blockIdx.y;              // channel
    const int n    = i + 1;                   // valid prefix length

    const float* src = scores + ((size_t)c * L + (size_t)i) * L;

    const int full = n >> 7;        // chunks [0,full) fully valid (128 cols each)
    const int base = lane << 2;

    float z[64];
    // branch-free predicated load pass: 16 consecutive @P LDG.128
#pragma unroll
    for (int t = 0; t < 16; t++) {
        if (t <= full) {
            *reinterpret_cast<float4*>(&z[4 * t]) =
                *reinterpret_cast<const float4*>(src + (t << 7) + base);
        }
    }
    // mask the partial chunk (static register indices; warp-uniform branch)
#pragma unroll
    for (int t = 0; t < 16; t++) {
        if (t == full) {
#pragma unroll
            for (int q = 0; q < 4; q++)
                if ((t << 7) + base + q >= n) z[4 * t + q] = -3.0e38f;
        }
    }

    // register-only sum + max pass
    float S = 0.f, M = -3.0e38f;
#pragma unroll
    for (int t = 0; t < 16; t++) {
        if (t > full) break;            // warp-uniform
#pragma unroll
        for (int q = 0; q < 4; q++) {
            float zz = z[4 * t + q];
            if (zz > -3.0e38f) S += zz;
            M = fmaxf(M, zz);
        }
    }
#pragma unroll
    for (int o = 16; o; o >>= 1) {
        S += __shfl_xor_sync(0xffffffffu, S, o);
        M = fmaxf(M, __shfl_xor_sync(0xffffffffu, M, o));
    }

    // tight start: tau* >= zmax - 1 (sum of (z-tau*)+ = 1 bounds zmax - tau*)
    float tau = fmaxf((S - 1.0f) / (float)n, M - 1.0f);
    float kprev = 3.0e38f;   // no break before first tau update

#pragma unroll 1
    for (int it = 0; it < 64; ++it) {
        float ls = 0.f, lc = 0.f;
#pragma unroll
        for (int t = 0; t < 16; t++) {
            if (t > full) break;        // warp-uniform
#pragma unroll
            for (int q = 0; q < 4; q++) {
                float zz = z[4 * t + q];
                if (zz > tau) { ls += zz; lc += 1.f; }
            }
        }
#pragma unroll
        for (int o = 16; o; o >>= 1) {
            ls += __shfl_xor_sync(0xffffffffu, ls, o);
            lc += __shfl_xor_sync(0xffffffffu, lc, o);
        }
        if (lc >= kprev || lc == 0.f) break;   // support stable -> fixed point
        tau = (ls - 1.0f) / lc;
        kprev = lc;
    }

    if (lane == 0) g_tau[(size_t)c * L + i] = tau;
}

// ---------------------------------------------------------------------------
// Kernel 2': grouped 3x3 conv + bias + causal zero, TWO output rows per block.
// Stages DIRECTLY FROM SCORES: p = (jj <= ii) ? max(z - tau[ch][ii], 0) : 0.
// Chunks are fully-valid-or-fully-OOB (j0 multiple of 512), so masking is a
// handful of predicated selects per float4 — no div/mod, no scratch array.
// Inner loop: scalar fp32 FMA (R9 form, ~86% of FFMA issue floor).
// grid = (4 tiles of 512, L/2 row-pairs, 4 groups), 128 threads.
// ---------------------------------------------------------------------------
__global__ void __launch_bounds__(128) conv3x3_group(const float* __restrict__ scores,
                                                     const float* __restrict__ weight,
                                                     const float* __restrict__ bias,
                                                     float* __restrict__ out) {
    const int g   = blockIdx.z;
    const int i0  = blockIdx.y * 2;
    const int j0  = blockIdx.x * 512;
    const int tid = threadIdx.x;

    if (j0 > i0 + 1) {  // both rows entirely above diagonal -> zeros
        const float4 z4 = make_float4(0.f, 0.f, 0.f, 0.f);
#pragma unroll
        for (int ro = 0; ro < 2; ro++)
#pragma unroll
            for (int co = 0; co < 4; co++) {
                size_t o = ((size_t)(g * 4 + co) * L + (size_t)(i0 + ro)) * L
                         + (size_t)(j0 + tid * 4);
                *reinterpret_cast<float4*>(out + o) = z4;
            }
        return;
    }

    __shared__ float s_in[16][528];   // fp32 planes: 520 used, stride-pad 528
    __shared__ float s_w[144];
    __shared__ float s_b[4];

    for (int e = tid; e < 144; e += 128) s_w[e] = weight[g * 144 + e];
    if (tid < 4) s_b[tid] = bias[g * 4 + tid];

    // staging: sparsemax-apply + causal mask fused into the copy.
    // smem col s holds jj = j0 - 4 + s; chunk c covers jj0 = j0 - 4 + 4c.
#pragma unroll
    for (int u = 0; u < 4; u++) {
        const int ch = g * 4 + u;
#pragma unroll
        for (int r = 0; r < 4; r++) {
            const int ii = i0 - 1 + r;                 // data row for this plane
            const bool rowok = (ii >= 0) && (ii < L);
            const float tv = rowok ? __ldg(&g_tau[(size_t)ch * L + ii]) : 0.f;
            const float* srow = scores + ((size_t)ch * L + (size_t)ii) * L;
            float4* dp = reinterpret_cast<float4*>(&s_in[u * 4 + r][0]);
#pragma unroll
            for (int h = 0; h < 2; h++) {
                const int cidx = h * 128 + tid;
                if (h == 1 && tid >= 2) break;
                const int jj0 = j0 - 4 + 4 * cidx;
                float4 v = make_float4(0.f, 0.f, 0.f, 0.f);
                if (rowok && jj0 >= 0 && jj0 < L) {    // chunk fully in-bounds
                    const float4 zv = *reinterpret_cast<const float4*>(srow + jj0);
                    const int d = ii - jj0;            // causal: keep q <= d
                    v.x = (d >= 0) ? fmaxf(zv.x - tv, 0.f) : 0.f;
                    v.y = (d >= 1) ? fmaxf(zv.y - tv, 0.f) : 0.f;
                    v.z = (d >= 2) ? fmaxf(zv.z - tv, 0.f) : 0.f;
                    v.w = (d >= 3) ? fmaxf(zv.w - tv, 0.f) : 0.f;
                }
                dp[cidx] = v;
            }
        }
    }
    __syncthreads();

    float acc[2][4][4];
#pragma unroll
    for (int ro = 0; ro < 2; ro++)
#pragma unroll
        for (int co = 0; co < 4; co++)
#pragma unroll
            for (int q = 0; q < 4; q++) acc[ro][co][q] = s_b[co];

#pragma unroll
    for (int u = 0; u < 4; u++) {
        float win[4][6];
#pragma unroll
        for (int r = 0; r < 4; r++) {
            const float4* rowp = reinterpret_cast<const float4*>(&s_in[u * 4 + r][0]);
            const float4 a = rowp[tid];
            const float4 b = rowp[tid + 1];
            const float4 cc = rowp[tid + 2];
            // v[m] = input at jj = colb - 1 + m, colb = j0 + 4*tid
            win[r][0] = a.w; win[r][1] = b.x; win[r][2] = b.y;
            win[r][3] = b.z; win[r][4] = b.w; win[r][5] = cc.x;
        }
#pragma unroll
        for (int ro = 0; ro < 2; ro++) {
#pragma unroll
            for (int kh = 0; kh < 3; kh++) {
                const float* v = win[ro + kh];
#pragma unroll
                for (int co = 0; co < 4; co++) {
                    const float w0 = s_w[co * 36 + u * 9 + kh * 3 + 0];
                    const float w1 = s_w[co * 36 + u * 9 + kh * 3 + 1];
                    const float w2 = s_w[co * 36 + u * 9 + kh * 3 + 2];
                    acc[ro][co][0] += v[0] * w0 + v[1] * w1 + v[2] * w2;
                    acc[ro][co][1] += v[1] * w0 + v[2] * w1 + v[3] * w2;
                    acc[ro][co][2] += v[2] * w0 + v[3] * w1 + v[4] * w2;
                    acc[ro][co][3] += v[3] * w0 + v[4] * w1 + v[5] * w2;
                }
            }
        }
    }

    const int colb = j0 + tid * 4;
#pragma unroll
    for (int ro = 0; ro < 2; ro++) {
        const int ii = i0 + ro;
#pragma unroll
        for (int co = 0; co < 4; co++) {
            float4 r4;
            r4.x = (colb + 0 <= ii) ? acc[ro][co][0] : 0.f;
            r4.y = (colb + 1 <= ii) ? acc[ro][co][1] : 0.f;
            r4.z = (colb + 2 <= ii) ? acc[ro][co][2] : 0.f;
            r4.w = (colb + 3 <= ii) ? acc[ro][co][3] : 0.f;
            size_t o = ((size_t)(g * 4 + co) * L + (size_t)ii) * L + (size_t)colb;
            *reinterpret_cast<float4*>(out + o) = r4;
        }
    }
}

extern "C" void kernel_launch(void* const* d_in, const int* in_sizes, int n_in,
                              void* d_out, int out_size) {
    const float* scores = (const float*)d_in[0];
    const float* weight = (const float*)d_in[1];
    const float* bias   = (const float*)d_in[2];
    float* out = (float*)d_out;

    sparsemax_tau<<<dim3(L / 8, CIN), 256>>>(scores);
    conv3x3_group<<<dim3(L / 512, L / 2, GROUPS), 128>>>(scores, weight, bias, out);
}

// round 15
// speedup vs baseline: 1.2828x; 1.2828x over previous
#include <cuda_runtime.h>

#define L 2048
#define CIN 16
#define GROUPS 4

// Tiny tau table: one threshold per (channel, row). 128 KB, L2-resident.
__device__ float g_tau[(size_t)CIN * L];

// ---------------------------------------------------------------------------
// Kernel 1': causal sparsemax THRESHOLD ONLY, one warp per row.
// 16 back-to-back predicated LDG.128 (MLP ~16); Michelot fixed point from
// tight tau0 = max((S-1)/n, max-1); shfl reductions. Writes 1 float per row.
// ---------------------------------------------------------------------------
__global__ void __launch_bounds__(256) sparsemax_tau(const float* __restrict__ scores) {
    const int tid  = threadIdx.x;
    const int w    = tid >> 5;
    const int lane = tid & 31;
    const int i    = (blockIdx.x << 3) + w;
    const int c    = blockIdx.y;
    const int n    = i + 1;

    const float* src = scores + ((size_t)c * L + (size_t)i) * L;

    const int full = n >> 7;
    const int base = lane << 2;

    float z[64];
#pragma unroll
    for (int t = 0; t < 16; t++) {
        if (t <= full) {
            *reinterpret_cast<float4*>(&z[4 * t]) =
                *reinterpret_cast<const float4*>(src + (t << 7) + base);
        }
    }
#pragma unroll
    for (int t = 0; t < 16; t++) {
        if (t == full) {
#pragma unroll
            for (int q = 0; q < 4; q++)
                if ((t << 7) + base + q >= n) z[4 * t + q] = -3.0e38f;
        }
    }

    float S = 0.f, M = -3.0e38f;
#pragma unroll
    for (int t = 0; t < 16; t++) {
        if (t > full) break;
#pragma unroll
        for (int q = 0; q < 4; q++) {
            float zz = z[4 * t + q];
            if (zz > -3.0e38f) S += zz;
            M = fmaxf(M, zz);
        }
    }
#pragma unroll
    for (int o = 16; o; o >>= 1) {
        S += __shfl_xor_sync(0xffffffffu, S, o);
        M = fmaxf(M, __shfl_xor_sync(0xffffffffu, M, o));
    }

    float tau = fmaxf((S - 1.0f) / (float)n, M - 1.0f);
    float kprev = 3.0e38f;

#pragma unroll 1
    for (int it = 0; it < 64; ++it) {
        float ls = 0.f, lc = 0.f;
#pragma unroll
        for (int t = 0; t < 16; t++) {
            if (t > full) break;
#pragma unroll
            for (int q = 0; q < 4; q++) {
                float zz = z[4 * t + q];
                if (zz > tau) { ls += zz; lc += 1.f; }
            }
        }
#pragma unroll
        for (int o = 16; o; o >>= 1) {
            ls += __shfl_xor_sync(0xffffffffu, ls, o);
            lc += __shfl_xor_sync(0xffffffffu, lc, o);
        }
        if (lc >= kprev || lc == 0.f) break;
        tau = (ls - 1.0f) / lc;
        kprev = lc;
    }

    if (lane == 0) g_tau[(size_t)c * L + i] = tau;
}

// ---------------------------------------------------------------------------
// Kernel 2': grouped 3x3 conv + bias + causal zero, TWO output rows per block.
// Staging from scores is BRANCH-FREE: addresses clamped so every LDG.128 is
// unconditional (batched, MLP 4-8/u); sparsemax-apply + masks are predicated
// selects. Warps wholly above the diagonal skip the FMA loop (store zeros).
// grid = (4 tiles of 512, L/2 row-pairs, 4 groups), 128 threads.
// ---------------------------------------------------------------------------
__global__ void __launch_bounds__(128) conv3x3_group(const float* __restrict__ scores,
                                                     const float* __restrict__ weight,
                                                     const float* __restrict__ bias,
                                                     float* __restrict__ out) {
    const int g   = blockIdx.z;
    const int i0  = blockIdx.y * 2;
    const int j0  = blockIdx.x * 512;
    const int tid = threadIdx.x;

    if (j0 > i0 + 1) {  // both rows entirely above diagonal -> zeros
        const float4 z4 = make_float4(0.f, 0.f, 0.f, 0.f);
#pragma unroll
        for (int ro = 0; ro < 2; ro++)
#pragma unroll
            for (int co = 0; co < 4; co++) {
                size_t o = ((size_t)(g * 4 + co) * L + (size_t)(i0 + ro)) * L
                         + (size_t)(j0 + tid * 4);
                *reinterpret_cast<float4*>(out + o) = z4;
            }
        return;
    }

    __shared__ float s_in[16][528];   // fp32 planes: 520 used, stride-pad 528
    __shared__ float s_w[144];
    __shared__ float s_b[4];

    for (int e = tid; e < 144; e += 128) s_w[e] = weight[g * 144 + e];
    if (tid < 4) s_b[tid] = bias[g * 4 + tid];

    // ---- branch-free staging: clamp addresses, mask values ----
    // smem col s holds jj = j0 - 4 + s. main chunk: cidx=tid; tail: tid<2.
    const int jj0m = j0 - 4 + 4 * tid;
    const int jjcm = min(max(jj0m, 0), L - 4);
    const int jj0t = j0 - 4 + 4 * (128 + tid);
    const int jjct = min(max(jj0t, 0), L - 4);

#pragma unroll
    for (int u = 0; u < 4; u++) {
        const int ch = g * 4 + u;
        float4 mv[4], tvv[4];
        float  tv[4];
        int    iiA[4];
        bool   rok[4];
        // batched unconditional loads (4 main, + up to 4 tail for tid<2)
#pragma unroll
        for (int r = 0; r < 4; r++) {
            const int ii = i0 - 1 + r;
            iiA[r] = ii;
            rok[r] = (ii >= 0) && (ii < L);
            const int iic = min(max(ii, 0), L - 1);
            tv[r] = __ldg(&g_tau[(size_t)ch * L + iic]);
            const float* srow = scores + ((size_t)ch * L + (size_t)iic) * L;
            mv[r] = *reinterpret_cast<const float4*>(srow + jjcm);
            if (tid < 2)
                tvv[r] = *reinterpret_cast<const float4*>(srow + jjct);
        }
        // mask + store
#pragma unroll
        for (int r = 0; r < 4; r++) {
            float4* dp = reinterpret_cast<float4*>(&s_in[u * 4 + r][0]);
            {
                const bool ok = rok[r] && (jj0m >= 0);
                const int d = iiA[r] - jj0m;
                float4 v;
                v.x = (ok && d >= 0) ? fmaxf(mv[r].x - tv[r], 0.f) : 0.f;
                v.y = (ok && d >= 1) ? fmaxf(mv[r].y - tv[r], 0.f) : 0.f;
                v.z = (ok && d >= 2) ? fmaxf(mv[r].z - tv[r], 0.f) : 0.f;
                v.w = (ok && d >= 3) ? fmaxf(mv[r].w - tv[r], 0.f) : 0.f;
                dp[tid] = v;
            }
            if (tid < 2) {
                const bool ok = rok[r] && (jj0t >= 0);
                const int d = iiA[r] - jj0t;
                float4 v;
                v.x = (ok && d >= 0) ? fmaxf(tvv[r].x - tv[r], 0.f) : 0.f;
                v.y = (ok && d >= 1) ? fmaxf(tvv[r].y - tv[r], 0.f) : 0.f;
                v.z = (ok && d >= 2) ? fmaxf(tvv[r].z - tv[r], 0.f) : 0.f;
                v.w = (ok && d >= 3) ? fmaxf(tvv[r].w - tv[r], 0.f) : 0.f;
                dp[128 + tid] = v;
            }
        }
    }
    __syncthreads();

    const int colb = j0 + tid * 4;

    // warp-level diagonal skip: this warp's cols all above i0+1 -> zeros only
    const int warp_lo = j0 + ((tid >> 5) << 7);
    if (warp_lo > i0 + 1) {
        const float4 z4 = make_float4(0.f, 0.f, 0.f, 0.f);
#pragma unroll
        for (int ro = 0; ro < 2; ro++)
#pragma unroll
            for (int co = 0; co < 4; co++) {
                size_t o = ((size_t)(g * 4 + co) * L + (size_t)(i0 + ro)) * L
                         + (size_t)colb;
                *reinterpret_cast<float4*>(out + o) = z4;
            }
        return;
    }

    float acc[2][4][4];
#pragma unroll
    for (int ro = 0; ro < 2; ro++)
#pragma unroll
        for (int co = 0; co < 4; co++)
#pragma unroll
            for (int q = 0; q < 4; q++) acc[ro][co][q] = s_b[co];

#pragma unroll
    for (int u = 0; u < 4; u++) {
        float win[4][6];
#pragma unroll
        for (int r = 0; r < 4; r++) {
            const float4* rowp = reinterpret_cast<const float4*>(&s_in[u * 4 + r][0]);
            const float4 a = rowp[tid];
            const float4 b = rowp[tid + 1];
            const float4 cc = rowp[tid + 2];
            win[r][0] = a.w; win[r][1] = b.x; win[r][2] = b.y;
            win[r][3] = b.z; win[r][4] = b.w; win[r][5] = cc.x;
        }
#pragma unroll
        for (int ro = 0; ro < 2; ro++) {
#pragma unroll
            for (int kh = 0; kh < 3; kh++) {
                const float* v = win[ro + kh];
#pragma unroll
                for (int co = 0; co < 4; co++) {
                    const float w0 = s_w[co * 36 + u * 9 + kh * 3 + 0];
                    const float w1 = s_w[co * 36 + u * 9 + kh * 3 + 1];
                    const float w2 = s_w[co * 36 + u * 9 + kh * 3 + 2];
                    acc[ro][co][0] += v[0] * w0 + v[1] * w1 + v[2] * w2;
                    acc[ro][co][1] += v[1] * w0 + v[2] * w1 + v[3] * w2;
                    acc[ro][co][2] += v[2] * w0 + v[3] * w1 + v[4] * w2;
                    acc[ro][co][3] += v[3] * w0 + v[4] * w1 + v[5] * w2;
                }
            }
        }
    }

#pragma unroll
    for (int ro = 0; ro < 2; ro++) {
        const int ii = i0 + ro;
#pragma unroll
        for (int co = 0; co < 4; co++) {
            float4 r4;
            r4.x = (colb + 0 <= ii) ? acc[ro][co][0] : 0.f;
            r4.y = (colb + 1 <= ii) ? acc[ro][co][1] : 0.f;
            r4.z = (colb + 2 <= ii) ? acc[ro][co][2] : 0.f;
            r4.w = (colb + 3 <= ii) ? acc[ro][co][3] : 0.f;
            size_t o = ((size_t)(g * 4 + co) * L + (size_t)ii) * L + (size_t)colb;
            *reinterpret_cast<float4*>(out + o) = r4;
        }
    }
}

extern "C" void kernel_launch(void* const* d_in, const int* in_sizes, int n_in,
                              void* d_out, int out_size) {
    const float* scores = (const float*)d_in[0];
    const float* weight = (const float*)d_in[1];
    const float* bias   = (const float*)d_in[2];
    float* out = (float*)d_out;

    sparsemax_tau<<<dim3(L / 8, CIN), 256>>>(scores);
    conv3x3_group<<<dim3(L / 512, L / 2, GROUPS), 128>>>(scores, weight, bias, out);
}

// round 16
// speedup vs baseline: 1.6305x; 1.2710x over previous
#include <cuda_runtime.h>
#include <cuda_fp16.h>

#define L 2048
#define CIN 16
#define GROUPS 4
#define LS 2056              // padded scratch row stride in HALVES: 4 lead + 2048 + 4 trail
#define ROWS_P (L + 2)       // +1 zero guard row above and below per channel

// ~135 MiB fp16 scratch. Channel c, padded row r holds data row r-1 (rows 0
// and L+1 zero guards). Cols: [0,4) lead pad, [4,4+L) data, trail pad.
// Above-diagonal cols zero-filled through the last 512-tile any conv consumer
// reads, so conv staging is fully branch-free.
__device__ __half g_probs[(size_t)CIN * ROWS_P * LS];

// ---------------------------------------------------------------------------
// Kernel 1: causal sparsemax, ONE WARP PER ROW. (R9 winner, unchanged)
// 16 back-to-back predicated LDG.128 (MLP ~16); Michelot fixed point from
// tight tau0 = max((S-1)/n, max-1); shfl reductions; vectorized store+fill.
// ---------------------------------------------------------------------------
__global__ void __launch_bounds__(256) sparsemax_rows(const float* __restrict__ scores) {
    const int tid  = threadIdx.x;
    const int w    = tid >> 5;
    const int lane = tid & 31;
    const int i    = (blockIdx.x << 3) + w;
    const int c    = blockIdx.y;
    const int n    = i + 1;

    const float* src = scores + ((size_t)c * L + (size_t)i) * L;
    __half* dst = g_probs + ((size_t)c * ROWS_P + (size_t)(i + 1)) * LS + 4;

    const int full = n >> 7;
    const int base = lane << 2;

    float z[64];
#pragma unroll
    for (int t = 0; t < 16; t++) {
        if (t <= full) {
            *reinterpret_cast<float4*>(&z[4 * t]) =
                *reinterpret_cast<const float4*>(src + (t << 7) + base);
        }
    }
#pragma unroll
    for (int t = 0; t < 16; t++) {
        if (t == full) {
#pragma unroll
            for (int q = 0; q < 4; q++)
                if ((t << 7) + base + q >= n) z[4 * t + q] = -3.0e38f;
        }
    }

    float S = 0.f, M = -3.0e38f;
#pragma unroll
    for (int t = 0; t < 16; t++) {
        if (t > full) break;
#pragma unroll
        for (int q = 0; q < 4; q++) {
            float zz = z[4 * t + q];
            if (zz > -3.0e38f) S += zz;
            M = fmaxf(M, zz);
        }
    }
#pragma unroll
    for (int o = 16; o; o >>= 1) {
        S += __shfl_xor_sync(0xffffffffu, S, o);
        M = fmaxf(M, __shfl_xor_sync(0xffffffffu, M, o));
    }

    float tau = fmaxf((S - 1.0f) / (float)n, M - 1.0f);
    float kprev = 3.0e38f;

#pragma unroll 1
    for (int it = 0; it < 64; ++it) {
        float ls = 0.f, lc = 0.f;
#pragma unroll
        for (int t = 0; t < 16; t++) {
            if (t > full) break;
#pragma unroll
            for (int q = 0; q < 4; q++) {
                float zz = z[4 * t + q];
                if (zz > tau) { ls += zz; lc += 1.f; }
            }
        }
#pragma unroll
        for (int o = 16; o; o >>= 1) {
            ls += __shfl_xor_sync(0xffffffffu, ls, o);
            lc += __shfl_xor_sync(0xffffffffu, lc, o);
        }
        if (lc >= kprev || lc == 0.f) break;
        tau = (ls - 1.0f) / lc;
        kprev = lc;
    }

    const int E  = min(2052, ((((n + 1) >> 9) << 9) + 516));
    const int EC = (E + 127) >> 7;
#pragma unroll
    for (int t = 0; t < 16; t++) {
        if (t < full) {
            __half2 h0 = __floats2half2_rn(fmaxf(z[4 * t + 0] - tau, 0.f),
                                           fmaxf(z[4 * t + 1] - tau, 0.f));
            __half2 h1 = __floats2half2_rn(fmaxf(z[4 * t + 2] - tau, 0.f),
                                           fmaxf(z[4 * t + 3] - tau, 0.f));
            uint2 pk;
            pk.x = *reinterpret_cast<unsigned*>(&h0);
            pk.y = *reinterpret_cast<unsigned*>(&h1);
            *reinterpret_cast<uint2*>(dst + (t << 7) + base) = pk;
        } else if (t == full) {
            float p0 = ((t << 7) + base + 0 < n) ? fmaxf(z[4 * t + 0] - tau, 0.f) : 0.f;
            float p1 = ((t << 7) + base + 1 < n) ? fmaxf(z[4 * t + 1] - tau, 0.f) : 0.f;
            float p2 = ((t << 7) + base + 2 < n) ? fmaxf(z[4 * t + 2] - tau, 0.f) : 0.f;
            float p3 = ((t << 7) + base + 3 < n) ? fmaxf(z[4 * t + 3] - tau, 0.f) : 0.f;
            __half2 h0 = __floats2half2_rn(p0, p1);
            __half2 h1 = __floats2half2_rn(p2, p3);
            uint2 pk;
            pk.x = *reinterpret_cast<unsigned*>(&h0);
            pk.y = *reinterpret_cast<unsigned*>(&h1);
            *reinterpret_cast<uint2*>(dst + (t << 7) + base) = pk;
        } else if (t < EC) {
            *reinterpret_cast<uint2*>(dst + (t << 7) + base) = make_uint2(0u, 0u);
        }
    }
    if (lane == 0) {
        *reinterpret_cast<uint2*>(dst - 4) = make_uint2(0u, 0u);
        if (E > 2048) *reinterpret_cast<uint2*>(dst + 2048) = make_uint2(0u, 0u);
    }
    if (i == 0) {
        uint4* gr = reinterpret_cast<uint4*>(g_probs + (size_t)c * ROWS_P * LS);
        const uint4 z4 = make_uint4(0u, 0u, 0u, 0u);
        for (int j = lane; j < LS / 8; j += 32) gr[j] = z4;
    }
    if (i == L - 1) {
        uint4* gr = reinterpret_cast<uint4*>(
            g_probs + ((size_t)c * ROWS_P + (size_t)(L + 1)) * LS);
        const uint4 z4 = make_uint4(0u, 0u, 0u, 0u);
        for (int j = lane; j < LS / 8; j += 32) gr[j] = z4;
    }
}

// ---------------------------------------------------------------------------
// Kernel 2: grouped 3x3 conv + bias + causal zero, TWO output rows per block.
// R9 winner + WARP-LEVEL DIAGONAL SKIP: warps whose 128-col span lies wholly
// above the diagonal store zeros and exit (removes ~20% of all FFMA work).
// Stages 4 input rows (16 planes) fp16->fp32 into smem; inner loop fp32 FMA.
// grid = (4 tiles of 512, L/2 row-pairs, 4 groups), 128 threads.
// ---------------------------------------------------------------------------
__global__ void __launch_bounds__(128) conv3x3_group(const float* __restrict__ weight,
                                                     const float* __restrict__ bias,
                                                     float* __restrict__ out) {
    const int g   = blockIdx.z;
    const int i0  = blockIdx.y * 2;
    const int j0  = blockIdx.x * 512;
    const int tid = threadIdx.x;

    if (j0 > i0 + 1) {  // both rows entirely above diagonal -> zeros
        const float4 z4 = make_float4(0.f, 0.f, 0.f, 0.f);
#pragma unroll
        for (int ro = 0; ro < 2; ro++)
#pragma unroll
            for (int co = 0; co < 4; co++) {
                size_t o = ((size_t)(g * 4 + co) * L + (size_t)(i0 + ro)) * L
                         + (size_t)(j0 + tid * 4);
                *reinterpret_cast<float4*>(out + o) = z4;
            }
        return;
    }

    __shared__ float s_in[16][528];   // fp32 planes: 520 used, stride-pad 528
    __shared__ float s_w[144];
    __shared__ float s_b[4];

    for (int e = tid; e < 144; e += 128) s_w[e] = weight[g * 144 + e];
    if (tid < 4) s_b[tid] = bias[g * 4 + tid];

    // staging: LDG.64 of 4 halves -> convert -> STS.128 float4. 130 per plane.
#pragma unroll
    for (int u = 0; u < 4; u++) {
#pragma unroll
        for (int r = 0; r < 4; r++) {
            const uint2* src = reinterpret_cast<const uint2*>(
                g_probs + ((size_t)(g * 4 + u) * ROWS_P + (size_t)(i0 + r)) * LS + (size_t)j0);
            float4* dp = reinterpret_cast<float4*>(&s_in[u * 4 + r][0]);
            {
                uint2 v = src[tid];
                float2 f0 = __half22float2(*reinterpret_cast<__half2*>(&v.x));
                float2 f1 = __half22float2(*reinterpret_cast<__half2*>(&v.y));
                dp[tid] = make_float4(f0.x, f0.y, f1.x, f1.y);
            }
            if (tid < 2) {
                uint2 v = src[128 + tid];
                float2 f0 = __half22float2(*reinterpret_cast<__half2*>(&v.x));
                float2 f1 = __half22float2(*reinterpret_cast<__half2*>(&v.y));
                dp[128 + tid] = make_float4(f0.x, f0.y, f1.x, f1.y);
            }
        }
    }
    __syncthreads();

    const int colb = j0 + tid * 4;

    // WARP-LEVEL DIAGONAL SKIP: this warp's lowest column is warp_lo; if even
    // that exceeds i0+1, every output this warp owns is causally zero.
    const int warp_lo = j0 + ((tid & ~31) << 2);   // j0 + 128*(warp id)
    if (warp_lo > i0 + 1) {
        const float4 z4 = make_float4(0.f, 0.f, 0.f, 0.f);
#pragma unroll
        for (int ro = 0; ro < 2; ro++)
#pragma unroll
            for (int co = 0; co < 4; co++) {
                size_t o = ((size_t)(g * 4 + co) * L + (size_t)(i0 + ro)) * L
                         + (size_t)colb;
                *reinterpret_cast<float4*>(out + o) = z4;
            }
        return;   // no __syncthreads below; safe to exit early
    }

    float acc[2][4][4];
#pragma unroll
    for (int ro = 0; ro < 2; ro++)
#pragma unroll
        for (int co = 0; co < 4; co++)
#pragma unroll
            for (int q = 0; q < 4; q++) acc[ro][co][q] = s_b[co];

#pragma unroll
    for (int u = 0; u < 4; u++) {
        float win[4][6];
#pragma unroll
        for (int r = 0; r < 4; r++) {
            const float4* rowp = reinterpret_cast<const float4*>(&s_in[u * 4 + r][0]);
            const float4 a = rowp[tid];
            const float4 b = rowp[tid + 1];
            const float4 cc = rowp[tid + 2];
            win[r][0] = a.w; win[r][1] = b.x; win[r][2] = b.y;
            win[r][3] = b.z; win[r][4] = b.w; win[r][5] = cc.x;
        }
#pragma unroll
        for (int ro = 0; ro < 2; ro++) {
#pragma unroll
            for (int kh = 0; kh < 3; kh++) {
                const float* v = win[ro + kh];
#pragma unroll
                for (int co = 0; co < 4; co++) {
                    const float w0 = s_w[co * 36 + u * 9 + kh * 3 + 0];
                    const float w1 = s_w[co * 36 + u * 9 + kh * 3 + 1];
                    const float w2 = s_w[co * 36 + u * 9 + kh * 3 + 2];
                    acc[ro][co][0] += v[0] * w0 + v[1] * w1 + v[2] * w2;
                    acc[ro][co][1] += v[1] * w0 + v[2] * w1 + v[3] * w2;
                    acc[ro][co][2] += v[2] * w0 + v[3] * w1 + v[4] * w2;
                    acc[ro][co][3] += v[3] * w0 + v[4] * w1 + v[5] * w2;
                }
            }
        }
    }

#pragma unroll
    for (int ro = 0; ro < 2; ro++) {
        const int ii = i0 + ro;
#pragma unroll
        for (int co = 0; co < 4; co++) {
            float4 r4;
            r4.x = (colb + 0 <= ii) ? acc[ro][co][0] : 0.f;
            r4.y = (colb + 1 <= ii) ? acc[ro][co][1] : 0.f;
            r4.z = (colb + 2 <= ii) ? acc[ro][co][2] : 0.f;
            r4.w = (colb + 3 <= ii) ? acc[ro][co][3] : 0.f;
            size_t o = ((size_t)(g * 4 + co) * L + (size_t)ii) * L + (size_t)colb;
            *reinterpret_cast<float4*>(out + o) = r4;
        }
    }
}

extern "C" void kernel_launch(void* const* d_in, const int* in_sizes, int n_in,
                              void* d_out, int out_size) {
    const float* scores = (const float*)d_in[0];
    const float* weight = (const float*)d_in[1];
    const float* bias   = (const float*)d_in[2];
    float* out = (float*)d_out;

    sparsemax_rows<<<dim3(L / 8, CIN), 256>>>(scores);
    conv3x3_group<<<dim3(L / 512, L / 2, GROUPS), 128>>>(weight, bias, out);
}